// round 7
// baseline (speedup 1.0000x reference)
#include <cuda_runtime.h>
#include <math.h>

#define B_ 4
#define N_ 10000
#define E_ 160000
#define F_ 64
#define D_ 128
#define H_ 4

// ---------------- scratch (static device globals; no allocation) ------------
__device__ float g_h0[B_ * N_ * D_];
__device__ float g_h1[B_ * N_ * D_];
__device__ float g_gbuf[B_ * N_ * D_];
__device__ float g_es[B_ * N_ * H_];
__device__ float g_ed[B_ * N_ * H_];
__device__ int   g_deg[B_ * N_];
__device__ int   g_rowptr[B_ * (N_ + 1)];
__device__ int   g_fill[B_ * N_];
__device__ int   g_csr[B_ * E_];
__device__ float g_gacc[B_ * D_];
__device__ float g_msum[B_];

// ---------------- zero init (deterministic per launch) ----------------------
__global__ void zero_kernel() {
    int i = blockIdx.x * blockDim.x + threadIdx.x;
    if (i < B_ * N_) g_deg[i] = 0;
    if (i < B_ * D_) g_gacc[i] = 0.f;
    if (i < B_) g_msum[i] = 0.f;
}

// ---------------- CSR build: count -> scan -> scatter -----------------------
__global__ void count_kernel(const int* __restrict__ ei) {
    int i = blockIdx.x * blockDim.x + threadIdx.x;
    if (i >= B_ * E_) return;
    int b = i / E_, e = i - b * E_;
    int dst = ei[b * 2 * E_ + E_ + e];
    atomicAdd(&g_deg[b * N_ + dst], 1);
}

__global__ void scan_kernel() {
    int b = blockIdx.x;
    __shared__ int s[256];
    __shared__ int carry;
    if (threadIdx.x == 0) carry = 0;
    __syncthreads();
    for (int base = 0; base < N_; base += 256) {
        int i = base + threadIdx.x;
        int v = (i < N_) ? g_deg[b * N_ + i] : 0;
        s[threadIdx.x] = v;
        __syncthreads();
        for (int off = 1; off < 256; off <<= 1) {
            int t = (threadIdx.x >= off) ? s[threadIdx.x - off] : 0;
            __syncthreads();
            s[threadIdx.x] += t;
            __syncthreads();
        }
        int excl = s[threadIdx.x] - v;
        if (i < N_) {
            int p = carry + excl;
            g_rowptr[b * (N_ + 1) + i] = p;
            g_fill[b * N_ + i] = p;
        }
        __syncthreads();
        if (threadIdx.x == 255) carry += s[255];
        __syncthreads();
    }
    if (threadIdx.x == 0) g_rowptr[b * (N_ + 1) + N_] = carry;
}

__global__ void scatter_kernel(const int* __restrict__ ei) {
    int i = blockIdx.x * blockDim.x + threadIdx.x;
    if (i >= B_ * E_) return;
    int b = i / E_, e = i - b * E_;
    int src = ei[b * 2 * E_ + e];
    int dst = ei[b * 2 * E_ + E_ + e];
    int pos = atomicAdd(&g_fill[b * N_ + dst], 1);
    g_csr[(size_t)b * E_ + pos] = src;
}

// ---------------- SGEMM: C[M,128] = A[M,K] @ W[K,128] + bias (+type embed) --
// BM=64, BN=128, BK=16, 256 threads, TM=4, TN=8
__global__ __launch_bounds__(256, 2) void gemm_kernel(
    const float* __restrict__ A, const float* __restrict__ W,
    const float* __restrict__ bias, float* __restrict__ C,
    int M, int K,
    const int* __restrict__ types, const float* __restrict__ tembed)
{
    __shared__ float As[16][64];
    __shared__ float Ws[16][128];
    const int tid = threadIdx.x;
    const int tr = tid >> 4;          // 0..15 -> rows tr*4..
    const int tc = tid & 15;          // 0..15 -> cols tc*8..
    const int row0 = blockIdx.x * 64;
    const int arow = tid >> 2;        // 0..63
    const int ac4 = (tid & 3) * 4;    // 0,4,8,12

    float acc[4][8];
#pragma unroll
    for (int i = 0; i < 4; i++)
#pragma unroll
        for (int j = 0; j < 8; j++) acc[i][j] = 0.f;

    for (int k0 = 0; k0 < K; k0 += 16) {
        float4 av = make_float4(0.f, 0.f, 0.f, 0.f);
        int grow = row0 + arow;
        if (grow < M) av = *(const float4*)(A + (size_t)grow * K + k0 + ac4);
        As[ac4 + 0][arow] = av.x;
        As[ac4 + 1][arow] = av.y;
        As[ac4 + 2][arow] = av.z;
        As[ac4 + 3][arow] = av.w;
#pragma unroll
        for (int it = 0; it < 2; it++) {
            int idx = tid + it * 256;        // 0..511
            int wr = idx >> 5;               // 0..15
            int wc = (idx & 31) * 4;         // 0..124
            *(float4*)(&Ws[wr][wc]) =
                *(const float4*)(W + (size_t)(k0 + wr) * 128 + wc);
        }
        __syncthreads();
#pragma unroll
        for (int k = 0; k < 16; k++) {
            float4 a = *(const float4*)(&As[k][tr * 4]);
            float4 b0 = *(const float4*)(&Ws[k][tc * 8]);
            float4 b1 = *(const float4*)(&Ws[k][tc * 8 + 4]);
            float aa[4] = {a.x, a.y, a.z, a.w};
            float bb[8] = {b0.x, b0.y, b0.z, b0.w, b1.x, b1.y, b1.z, b1.w};
#pragma unroll
            for (int i = 0; i < 4; i++)
#pragma unroll
                for (int j = 0; j < 8; j++) acc[i][j] += aa[i] * bb[j];
        }
        __syncthreads();
    }
    float4 bias0 = *(const float4*)(bias + tc * 8);
    float4 bias1 = *(const float4*)(bias + tc * 8 + 4);
#pragma unroll
    for (int i = 0; i < 4; i++) {
        int grow = row0 + tr * 4 + i;
        if (grow >= M) continue;
        float4 o0 = make_float4(acc[i][0] + bias0.x, acc[i][1] + bias0.y,
                                acc[i][2] + bias0.z, acc[i][3] + bias0.w);
        float4 o1 = make_float4(acc[i][4] + bias1.x, acc[i][5] + bias1.y,
                                acc[i][6] + bias1.z, acc[i][7] + bias1.w);
        if (types) {
            const float* te = tembed + (size_t)types[grow] * 128;
            float4 t0 = *(const float4*)(te + tc * 8);
            float4 t1 = *(const float4*)(te + tc * 8 + 4);
            o0.x += t0.x; o0.y += t0.y; o0.z += t0.z; o0.w += t0.w;
            o1.x += t1.x; o1.y += t1.y; o1.z += t1.z; o1.w += t1.w;
        }
        *(float4*)(C + (size_t)grow * 128 + tc * 8) = o0;
        *(float4*)(C + (size_t)grow * 128 + tc * 8 + 4) = o1;
    }
}

// ---------------- e_s / e_d per node: one warp per node ---------------------
__global__ void esed_kernel(const float* __restrict__ g,
                            const float* __restrict__ a_s,
                            const float* __restrict__ a_d) {
    int wid = (blockIdx.x * blockDim.x + threadIdx.x) >> 5;
    int lane = threadIdx.x & 31;
    if (wid >= B_ * N_) return;
    int head = lane >> 3;
    int kk = (lane & 7) * 4;
    float4 gv = *(const float4*)(g + (size_t)wid * D_ + lane * 4);
    float4 as = *(const float4*)(a_s + head * 32 + kk);
    float4 ad = *(const float4*)(a_d + head * 32 + kk);
    float ps = gv.x * as.x + gv.y * as.y + gv.z * as.z + gv.w * as.w;
    float pd = gv.x * ad.x + gv.y * ad.y + gv.z * ad.z + gv.w * ad.w;
#pragma unroll
    for (int off = 1; off < 8; off <<= 1) {
        ps += __shfl_xor_sync(0xffffffffu, ps, off);
        pd += __shfl_xor_sync(0xffffffffu, pd, off);
    }
    if ((lane & 7) == 0) {
        g_es[wid * H_ + head] = ps;
        g_ed[wid * H_ + head] = pd;
    }
}

// ---------------- GAT aggregation: warp/node, online softmax, no atomics ----
__global__ __launch_bounds__(256) void agg_kernel(const float* __restrict__ g,
                                                  const float* __restrict__ h_in,
                                                  const float* __restrict__ mask,
                                                  float* __restrict__ h_out) {
    int wid = (blockIdx.x * blockDim.x + threadIdx.x) >> 5;
    int lane = threadIdx.x & 31;
    if (wid >= B_ * N_) return;
    int b = wid / N_, n = wid - b * N_;
    const int* rp = g_rowptr + b * (N_ + 1);
    const int* cs = g_csr + (size_t)b * E_;
    const float* gb = g + (size_t)b * N_ * D_;
    const float* esb = g_es + (size_t)b * N_ * H_;
    int head = lane >> 3;
    float edh = g_ed[(size_t)wid * H_ + head];
    float m = -1e30f, d = 0.f;
    float4 acc = make_float4(0.f, 0.f, 0.f, 0.f);
    int s0 = rp[n], s1 = rp[n + 1];
    for (int p = s0; p < s1; p++) {
        int src = cs[p];
        float e = esb[src * H_ + head] + edh;
        e = e > 0.f ? e : 0.2f * e;          // leaky_relu(0.2)
        float mn = fmaxf(m, e);
        float sc = __expf(m - mn);
        float pw = __expf(e - mn);
        d = d * sc + pw;
        float4 gv = *(const float4*)(gb + (size_t)src * D_ + lane * 4);
        acc.x = acc.x * sc + pw * gv.x;
        acc.y = acc.y * sc + pw * gv.y;
        acc.z = acc.z * sc + pw * gv.z;
        acc.w = acc.w * sc + pw * gv.w;
        m = mn;
    }
    float inv = 1.f / (d + 1e-16f);
    float mk = mask[b * N_ + n];
    float4 hv = *(const float4*)(h_in + (size_t)wid * D_ + lane * 4);
    float4 o;
    float v;
    v = acc.x * inv + hv.x; o.x = (v > 0.f ? v : expm1f(v)) * mk;
    v = acc.y * inv + hv.y; o.y = (v > 0.f ? v : expm1f(v)) * mk;
    v = acc.z * inv + hv.z; o.z = (v > 0.f ? v : expm1f(v)) * mk;
    v = acc.w * inv + hv.w; o.w = (v > 0.f ? v : expm1f(v)) * mk;
    *(float4*)(h_out + (size_t)wid * D_ + lane * 4) = o;
}

// ---------------- graph embedding -------------------------------------------
__global__ void graph_accum_kernel(const float* __restrict__ node_emb,
                                   const float* __restrict__ mask) {
    int b = blockIdx.y;
    int o = threadIdx.x;          // 128
    int n0 = blockIdx.x * 250;
    int n1 = n0 + 250;
    float s = 0.f;
    for (int n = n0; n < n1; n++) {
        float mk = mask[b * N_ + n];
        s += node_emb[((size_t)(b * N_ + n)) * D_ + o] * mk;
    }
    atomicAdd(&g_gacc[b * D_ + o], s);
}

__global__ void msum_kernel(const float* __restrict__ mask) {
    int b = threadIdx.x >> 5;
    int lane = threadIdx.x & 31;
    if (b >= B_) return;
    float s = 0.f;
    for (int n = lane; n < N_; n += 32) s += mask[b * N_ + n];
#pragma unroll
    for (int off = 16; off > 0; off >>= 1) s += __shfl_xor_sync(0xffffffffu, s, off);
    if (lane == 0) g_msum[b] = s;
}

__global__ void finalize_kernel(float* __restrict__ out) {
    int i = blockIdx.x * blockDim.x + threadIdx.x;
    if (i >= B_ * D_) return;
    int b = i / D_;
    float ms = g_msum[b];
    ms = ms < 1.f ? 1.f : ms;
    out[(size_t)B_ * N_ * D_ + i] = g_gacc[i] / ms;
}

// ---------------- launch -----------------------------------------------------
static float* symf(const void* s) { void* p = nullptr; cudaGetSymbolAddress(&p, s); return (float*)p; }

extern "C" void kernel_launch(void* const* d_in, const int* in_sizes, int n_in,
                              void* d_out, int out_size) {
    const float* node_features = (const float*)d_in[0];
    const int*   edge_index    = (const int*)d_in[1];
    const int*   node_types    = (const int*)d_in[2];
    const float* node_mask     = (const float*)d_in[3];
    const float* type_embed    = (const float*)d_in[4];
    const float* in_W          = (const float*)d_in[5];
    const float* in_b          = (const float*)d_in[6];
    const float* gat_W         = (const float*)d_in[7];
    const float* gat_b         = (const float*)d_in[8];
    const float* a_src         = (const float*)d_in[9];
    const float* a_dst         = (const float*)d_in[10];
    const float* out_W         = (const float*)d_in[11];
    const float* out_b         = (const float*)d_in[12];
    float* out = (float*)d_out;

    float* h0   = symf(g_h0);
    float* h1   = symf(g_h1);
    float* gbuf = symf(g_gbuf);

    const int M = B_ * N_;

    // init + CSR build (dst is layer-invariant -> build once, reuse twice)
    zero_kernel<<<(B_ * N_ + 255) / 256, 256>>>();
    count_kernel<<<(B_ * E_ + 255) / 256, 256>>>(edge_index);
    scan_kernel<<<B_, 256>>>();
    scatter_kernel<<<(B_ * E_ + 255) / 256, 256>>>(edge_index);

    // input projection + type embedding
    gemm_kernel<<<(M + 63) / 64, 256>>>(node_features, in_W, in_b, h0,
                                        M, F_, node_types, type_embed);

    const int warps_grid = (B_ * N_ * 32 + 255) / 256;

    // layer 0
    gemm_kernel<<<(M + 63) / 64, 256>>>(h0, gat_W, gat_b, gbuf, M, D_,
                                        nullptr, nullptr);
    esed_kernel<<<warps_grid, 256>>>(gbuf, a_src, a_dst);
    agg_kernel<<<warps_grid, 256>>>(gbuf, h0, node_mask, h1);

    // layer 1
    gemm_kernel<<<(M + 63) / 64, 256>>>(h1, gat_W + D_ * D_, gat_b + D_, gbuf,
                                        M, D_, nullptr, nullptr);
    esed_kernel<<<warps_grid, 256>>>(gbuf, a_src + H_ * (D_ / H_),
                                     a_dst + H_ * (D_ / H_));
    agg_kernel<<<warps_grid, 256>>>(gbuf, h1, node_mask, h0);

    // output projection -> node_emb (directly into d_out)
    gemm_kernel<<<(M + 63) / 64, 256>>>(h0, out_W, out_b, out, M, D_,
                                        nullptr, nullptr);

    // graph embedding
    dim3 gg(40, B_);
    graph_accum_kernel<<<gg, 128>>>(out, node_mask);
    msum_kernel<<<1, 128>>>(node_mask);
    finalize_kernel<<<2, 256>>>(out);
}

// round 8
// speedup vs baseline: 1.0008x; 1.0008x over previous
#include <cuda_runtime.h>
#include <math.h>

#define B_ 4
#define N_ 10000
#define E_ 160000
#define F_ 64
#define D_ 128
#define H_ 4

// ---------------- scratch (static device globals; no allocation) ------------
__device__ float g_h0[B_ * N_ * D_];
__device__ float g_h1[B_ * N_ * D_];
__device__ float g_gbuf[B_ * N_ * D_];
__device__ float g_es[B_ * N_ * H_];
__device__ float g_ed[B_ * N_ * H_];
__device__ int   g_deg[B_ * N_];
__device__ int   g_rowptr[B_ * (N_ + 1)];
__device__ int   g_fill[B_ * N_];
__device__ int   g_csr[B_ * E_];
__device__ float g_gacc[B_ * D_];
__device__ float g_msum[B_];

// ---------------- zero init (deterministic per launch) ----------------------
__global__ void zero_kernel() {
    int i = blockIdx.x * blockDim.x + threadIdx.x;
    if (i < B_ * N_) g_deg[i] = 0;
    if (i < B_ * D_) g_gacc[i] = 0.f;
    if (i < B_) g_msum[i] = 0.f;
}

// ---------------- CSR build: count -> scan -> scatter -----------------------
__global__ void count_kernel(const int* __restrict__ ei) {
    int i = blockIdx.x * blockDim.x + threadIdx.x;
    if (i >= B_ * E_) return;
    int b = i / E_, e = i - b * E_;
    int dst = ei[b * 2 * E_ + E_ + e];
    atomicAdd(&g_deg[b * N_ + dst], 1);
}

__global__ void scan_kernel() {
    int b = blockIdx.x;
    __shared__ int s[256];
    __shared__ int carry;
    if (threadIdx.x == 0) carry = 0;
    __syncthreads();
    for (int base = 0; base < N_; base += 256) {
        int i = base + threadIdx.x;
        int v = (i < N_) ? g_deg[b * N_ + i] : 0;
        s[threadIdx.x] = v;
        __syncthreads();
        for (int off = 1; off < 256; off <<= 1) {
            int t = (threadIdx.x >= off) ? s[threadIdx.x - off] : 0;
            __syncthreads();
            s[threadIdx.x] += t;
            __syncthreads();
        }
        int excl = s[threadIdx.x] - v;
        if (i < N_) {
            int p = carry + excl;
            g_rowptr[b * (N_ + 1) + i] = p;
            g_fill[b * N_ + i] = p;
        }
        __syncthreads();
        if (threadIdx.x == 255) carry += s[255];
        __syncthreads();
    }
    if (threadIdx.x == 0) g_rowptr[b * (N_ + 1) + N_] = carry;
}

__global__ void scatter_kernel(const int* __restrict__ ei) {
    int i = blockIdx.x * blockDim.x + threadIdx.x;
    if (i >= B_ * E_) return;
    int b = i / E_, e = i - b * E_;
    int src = ei[b * 2 * E_ + e];
    int dst = ei[b * 2 * E_ + E_ + e];
    int pos = atomicAdd(&g_fill[b * N_ + dst], 1);
    g_csr[(size_t)b * E_ + pos] = src;
}

// ---------------- SGEMM: C[M,128] = A[M,K] @ W[K,128] + bias (+type embed) --
// BM=64, BN=128, BK=16, 256 threads, TM=4, TN=8
__global__ __launch_bounds__(256, 2) void gemm_kernel(
    const float* __restrict__ A, const float* __restrict__ W,
    const float* __restrict__ bias, float* __restrict__ C,
    int M, int K,
    const int* __restrict__ types, const float* __restrict__ tembed)
{
    __shared__ float As[16][64];
    __shared__ float Ws[16][128];
    const int tid = threadIdx.x;
    const int tr = tid >> 4;          // 0..15 -> rows tr*4..
    const int tc = tid & 15;          // 0..15 -> cols tc*8..
    const int row0 = blockIdx.x * 64;
    const int arow = tid >> 2;        // 0..63
    const int ac4 = (tid & 3) * 4;    // 0,4,8,12

    float acc[4][8];
#pragma unroll
    for (int i = 0; i < 4; i++)
#pragma unroll
        for (int j = 0; j < 8; j++) acc[i][j] = 0.f;

    for (int k0 = 0; k0 < K; k0 += 16) {
        float4 av = make_float4(0.f, 0.f, 0.f, 0.f);
        int grow = row0 + arow;
        if (grow < M) av = *(const float4*)(A + (size_t)grow * K + k0 + ac4);
        As[ac4 + 0][arow] = av.x;
        As[ac4 + 1][arow] = av.y;
        As[ac4 + 2][arow] = av.z;
        As[ac4 + 3][arow] = av.w;
#pragma unroll
        for (int it = 0; it < 2; it++) {
            int idx = tid + it * 256;        // 0..511
            int wr = idx >> 5;               // 0..15
            int wc = (idx & 31) * 4;         // 0..124
            *(float4*)(&Ws[wr][wc]) =
                *(const float4*)(W + (size_t)(k0 + wr) * 128 + wc);
        }
        __syncthreads();
#pragma unroll
        for (int k = 0; k < 16; k++) {
            float4 a = *(const float4*)(&As[k][tr * 4]);
            float4 b0 = *(const float4*)(&Ws[k][tc * 8]);
            float4 b1 = *(const float4*)(&Ws[k][tc * 8 + 4]);
            float aa[4] = {a.x, a.y, a.z, a.w};
            float bb[8] = {b0.x, b0.y, b0.z, b0.w, b1.x, b1.y, b1.z, b1.w};
#pragma unroll
            for (int i = 0; i < 4; i++)
#pragma unroll
                for (int j = 0; j < 8; j++) acc[i][j] += aa[i] * bb[j];
        }
        __syncthreads();
    }
    float4 bias0 = *(const float4*)(bias + tc * 8);
    float4 bias1 = *(const float4*)(bias + tc * 8 + 4);
#pragma unroll
    for (int i = 0; i < 4; i++) {
        int grow = row0 + tr * 4 + i;
        if (grow >= M) continue;
        float4 o0 = make_float4(acc[i][0] + bias0.x, acc[i][1] + bias0.y,
                                acc[i][2] + bias0.z, acc[i][3] + bias0.w);
        float4 o1 = make_float4(acc[i][4] + bias1.x, acc[i][5] + bias1.y,
                                acc[i][6] + bias1.z, acc[i][7] + bias1.w);
        if (types) {
            const float* te = tembed + (size_t)types[grow] * 128;
            float4 t0 = *(const float4*)(te + tc * 8);
            float4 t1 = *(const float4*)(te + tc * 8 + 4);
            o0.x += t0.x; o0.y += t0.y; o0.z += t0.z; o0.w += t0.w;
            o1.x += t1.x; o1.y += t1.y; o1.z += t1.z; o1.w += t1.w;
        }
        *(float4*)(C + (size_t)grow * 128 + tc * 8) = o0;
        *(float4*)(C + (size_t)grow * 128 + tc * 8 + 4) = o1;
    }
}

// ---------------- e_s / e_d per node: one warp per node ---------------------
__global__ void esed_kernel(const float* __restrict__ g,
                            const float* __restrict__ a_s,
                            const float* __restrict__ a_d) {
    int wid = (blockIdx.x * blockDim.x + threadIdx.x) >> 5;
    int lane = threadIdx.x & 31;
    if (wid >= B_ * N_) return;
    int head = lane >> 3;
    int kk = (lane & 7) * 4;
    float4 gv = *(const float4*)(g + (size_t)wid * D_ + lane * 4);
    float4 as = *(const float4*)(a_s + head * 32 + kk);
    float4 ad = *(const float4*)(a_d + head * 32 + kk);
    float ps = gv.x * as.x + gv.y * as.y + gv.z * as.z + gv.w * as.w;
    float pd = gv.x * ad.x + gv.y * ad.y + gv.z * ad.z + gv.w * ad.w;
#pragma unroll
    for (int off = 1; off < 8; off <<= 1) {
        ps += __shfl_xor_sync(0xffffffffu, ps, off);
        pd += __shfl_xor_sync(0xffffffffu, pd, off);
    }
    if ((lane & 7) == 0) {
        g_es[wid * H_ + head] = ps;
        g_ed[wid * H_ + head] = pd;
    }
}

// ---------------- GAT aggregation: warp/node, online softmax, no atomics ----
__global__ __launch_bounds__(256) void agg_kernel(const float* __restrict__ g,
                                                  const float* __restrict__ h_in,
                                                  const float* __restrict__ mask,
                                                  float* __restrict__ h_out) {
    int wid = (blockIdx.x * blockDim.x + threadIdx.x) >> 5;
    int lane = threadIdx.x & 31;
    if (wid >= B_ * N_) return;
    int b = wid / N_, n = wid - b * N_;
    const int* rp = g_rowptr + b * (N_ + 1);
    const int* cs = g_csr + (size_t)b * E_;
    const float* gb = g + (size_t)b * N_ * D_;
    const float* esb = g_es + (size_t)b * N_ * H_;
    int head = lane >> 3;
    float edh = g_ed[(size_t)wid * H_ + head];
    float m = -1e30f, d = 0.f;
    float4 acc = make_float4(0.f, 0.f, 0.f, 0.f);
    int s0 = rp[n], s1 = rp[n + 1];
    for (int p = s0; p < s1; p++) {
        int src = cs[p];
        float e = esb[src * H_ + head] + edh;
        e = e > 0.f ? e : 0.2f * e;          // leaky_relu(0.2)
        float mn = fmaxf(m, e);
        float sc = __expf(m - mn);
        float pw = __expf(e - mn);
        d = d * sc + pw;
        float4 gv = *(const float4*)(gb + (size_t)src * D_ + lane * 4);
        acc.x = acc.x * sc + pw * gv.x;
        acc.y = acc.y * sc + pw * gv.y;
        acc.z = acc.z * sc + pw * gv.z;
        acc.w = acc.w * sc + pw * gv.w;
        m = mn;
    }
    float inv = 1.f / (d + 1e-16f);
    float mk = mask[b * N_ + n];
    float4 hv = *(const float4*)(h_in + (size_t)wid * D_ + lane * 4);
    float4 o;
    float v;
    v = acc.x * inv + hv.x; o.x = (v > 0.f ? v : expm1f(v)) * mk;
    v = acc.y * inv + hv.y; o.y = (v > 0.f ? v : expm1f(v)) * mk;
    v = acc.z * inv + hv.z; o.z = (v > 0.f ? v : expm1f(v)) * mk;
    v = acc.w * inv + hv.w; o.w = (v > 0.f ? v : expm1f(v)) * mk;
    *(float4*)(h_out + (size_t)wid * D_ + lane * 4) = o;
}

// ---------------- graph embedding -------------------------------------------
__global__ void graph_accum_kernel(const float* __restrict__ node_emb,
                                   const float* __restrict__ mask) {
    int b = blockIdx.y;
    int o = threadIdx.x;          // 128
    int n0 = blockIdx.x * 250;
    int n1 = n0 + 250;
    float s = 0.f;
    for (int n = n0; n < n1; n++) {
        float mk = mask[b * N_ + n];
        s += node_emb[((size_t)(b * N_ + n)) * D_ + o] * mk;
    }
    atomicAdd(&g_gacc[b * D_ + o], s);
}

__global__ void msum_kernel(const float* __restrict__ mask) {
    int b = threadIdx.x >> 5;
    int lane = threadIdx.x & 31;
    if (b >= B_) return;
    float s = 0.f;
    for (int n = lane; n < N_; n += 32) s += mask[b * N_ + n];
#pragma unroll
    for (int off = 16; off > 0; off >>= 1) s += __shfl_xor_sync(0xffffffffu, s, off);
    if (lane == 0) g_msum[b] = s;
}

__global__ void finalize_kernel(float* __restrict__ out) {
    int i = blockIdx.x * blockDim.x + threadIdx.x;
    if (i >= B_ * D_) return;
    int b = i / D_;
    float ms = g_msum[b];
    ms = ms < 1.f ? 1.f : ms;
    out[(size_t)B_ * N_ * D_ + i] = g_gacc[i] / ms;
}

// ---------------- launch -----------------------------------------------------
static float* symf(const void* s) { void* p = nullptr; cudaGetSymbolAddress(&p, s); return (float*)p; }

extern "C" void kernel_launch(void* const* d_in, const int* in_sizes, int n_in,
                              void* d_out, int out_size) {
    const float* node_features = (const float*)d_in[0];
    const int*   edge_index    = (const int*)d_in[1];
    const int*   node_types    = (const int*)d_in[2];
    const float* node_mask     = (const float*)d_in[3];
    const float* type_embed    = (const float*)d_in[4];
    const float* in_W          = (const float*)d_in[5];
    const float* in_b          = (const float*)d_in[6];
    const float* gat_W         = (const float*)d_in[7];
    const float* gat_b         = (const float*)d_in[8];
    const float* a_src         = (const float*)d_in[9];
    const float* a_dst         = (const float*)d_in[10];
    const float* out_W         = (const float*)d_in[11];
    const float* out_b         = (const float*)d_in[12];
    float* out = (float*)d_out;

    float* h0   = symf(g_h0);
    float* h1   = symf(g_h1);
    float* gbuf = symf(g_gbuf);

    const int M = B_ * N_;

    // init + CSR build (dst is layer-invariant -> build once, reuse twice)
    zero_kernel<<<(B_ * N_ + 255) / 256, 256>>>();
    count_kernel<<<(B_ * E_ + 255) / 256, 256>>>(edge_index);
    scan_kernel<<<B_, 256>>>();
    scatter_kernel<<<(B_ * E_ + 255) / 256, 256>>>(edge_index);

    // input projection + type embedding
    gemm_kernel<<<(M + 63) / 64, 256>>>(node_features, in_W, in_b, h0,
                                        M, F_, node_types, type_embed);

    const int warps_grid = (B_ * N_ * 32 + 255) / 256;

    // layer 0
    gemm_kernel<<<(M + 63) / 64, 256>>>(h0, gat_W, gat_b, gbuf, M, D_,
                                        nullptr, nullptr);
    esed_kernel<<<warps_grid, 256>>>(gbuf, a_src, a_dst);
    agg_kernel<<<warps_grid, 256>>>(gbuf, h0, node_mask, h1);

    // layer 1
    gemm_kernel<<<(M + 63) / 64, 256>>>(h1, gat_W + D_ * D_, gat_b + D_, gbuf,
                                        M, D_, nullptr, nullptr);
    esed_kernel<<<warps_grid, 256>>>(gbuf, a_src + H_ * (D_ / H_),
                                     a_dst + H_ * (D_ / H_));
    agg_kernel<<<warps_grid, 256>>>(gbuf, h1, node_mask, h0);

    // output projection -> node_emb (directly into d_out)
    gemm_kernel<<<(M + 63) / 64, 256>>>(h0, out_W, out_b, out, M, D_,
                                        nullptr, nullptr);

    // graph embedding
    dim3 gg(40, B_);
    graph_accum_kernel<<<gg, 128>>>(out, node_mask);
    msum_kernel<<<1, 128>>>(node_mask);
    finalize_kernel<<<2, 256>>>(out);
}